// round 10
// baseline (speedup 1.0000x reference)
#include <cuda_runtime.h>
#include <math.h>

#define NODES 512
#define S     8
#define DIN   768
#define NN    4096
#define NB    148                  /* persistent blocks per matrix */
#define TPB   512
#define NWT   (NB * (TPB / 32))    /* warps per matrix = 2368 */
#define PW    8                    /* panel width */
#define CW    1024                 /* RMW column chunk */

#define KH(s, c, p) do {                                 \
    float _y = __fsub_rn((p), (c));                      \
    float _t = __fadd_rn((s), _y);                       \
    (c) = __fsub_rn(__fsub_rn(_t, (s)), _y);             \
    (s) = _t;                                            \
} while (0)

/* ------------------------------------------------------------------ */
__device__ float         g_X[2][NODES][S];
__device__ unsigned char g_adj[2][NODES][NODES];
__device__ __align__(16) float2 g_A[2][(size_t)NN * NN];
__device__ float         g_V[2][PW][NN];
__device__ float         g_Yp[2][PW][NN];
__device__ float         g_cand[2][NN];
__device__ double        g_nrm[2][NN];
__device__ double        g_alf[2][NN];
__device__ double        g_vt[2][NN];
__device__ double        g_d1[2][NN][PW];
__device__ double        g_d2[2][NN][PW];
__device__ double        g_diag[2][NN];
__device__ double        g_offd[2][NN];
__device__ float         g_eig[2][NN];
__device__ unsigned int  g_count[2];
__device__ unsigned int  g_gen[2];

/* ------------------------------------------------------------------ */
__device__ __forceinline__ void gridbar(int mat)
{
    __threadfence();
    __syncthreads();
    if (threadIdx.x == 0) {
        volatile unsigned int* genp = &g_gen[mat];
        unsigned int old = *genp;
        if (atomicAdd(&g_count[mat], 1u) == (unsigned)(NB - 1)) {
            atomicExch(&g_count[mat], 0u);
            __threadfence();
            atomicExch(&g_gen[mat], old + 1u);
        } else {
            while (*genp == old) __nanosleep(64);
        }
        __threadfence();
    }
    __syncthreads();
}

__device__ __forceinline__ void refl(int mat, int j,
                                     double& tau, double& beta, double& scale)
{
    double n = g_nrm[mat][j], a = g_alf[mat][j];
    if (n == 0.0) { tau = 0.0; beta = a; scale = 0.0; }
    else {
        beta  = -copysign(sqrt(a * a + n), a);
        tau   = (beta - a) / beta;
        scale = 1.0 / (a - beta);
    }
}

/* ------------------------------------------------------------------ */
__global__ __launch_bounds__(256) void k_proj(const float* __restrict__ q,
                                              const float* __restrict__ pos,
                                              const float* __restrict__ neg,
                                              const float* __restrict__ W)
{
    int b     = blockIdx.x;
    int cloud = b >> 9;
    int row   = b & 511;
    const float* src = (row < 256) ? (q + (size_t)row * DIN)
                                   : ((cloud == 0 ? pos : neg) + (size_t)(row - 256) * DIN);
    __shared__ float sm[256];
    int t = threadIdx.x;
    int c = t & 7;
    int g = t >> 3;
    float acc = 0.f;
    for (int j = g; j < DIN; j += 32)
        acc += src[j] * W[c * DIN + j];
    sm[t] = acc;
    __syncthreads();
    for (int off = 128; off >= 8; off >>= 1) {
        if (t < off) sm[t] += sm[t + off];
        __syncthreads();
    }
    if (t < 8) g_X[cloud][row][t] = sm[t];

    int* adj32 = (int*)g_adj;
    int  base  = b * 128;
    for (int i = t; i < 128; i += 256) adj32[base + i] = 0;
}

/* ------------------------------------------------------------------ */
__global__ __launch_bounds__(256) void k_knn()
{
    int b     = blockIdx.x;
    int cloud = b >> 9;
    int i     = b & 511;
    __shared__ float sX[NODES][S];
    __shared__ float sd[NODES];
    int t = threadIdx.x;
    for (int idx = t; idx < NODES * S; idx += 256)
        ((float*)sX)[idx] = ((const float*)g_X[cloud])[idx];
    __syncthreads();
    for (int j = t; j < NODES; j += 256) {
        float d2 = 0.f;
        #pragma unroll
        for (int c = 0; c < S; c++) {
            float d = sX[j][c] - sX[i][c];
            d2 += d * d;
        }
        sd[j] = (j == i) ? 3.4e38f : d2;
    }
    __syncthreads();
    if (t == 0) {
        for (int p = 0; p < 5; p++) {
            float best = 3.4e38f;
            int   bj   = 0;
            for (int j = 0; j < NODES; j++)
                if (sd[j] < best) { best = sd[j]; bj = j; }
            sd[bj] = 3.4e38f;
            g_adj[cloud][i][bj] = 1;
            g_adj[cloud][bj][i] = 1;
        }
    }
}

/* ------------------------------------------------------------------ */
__global__ __launch_bounds__(256) void k_assemble()
{
    int i     = blockIdx.x;
    int cloud = blockIdx.y;
    __shared__ float         sX[NODES][S];
    __shared__ unsigned char sadj[NODES];
    __shared__ double        sdiag[64];
    int t = threadIdx.x;
    for (int idx = t; idx < NODES * S; idx += 256)
        ((float*)sX)[idx] = ((const float*)g_X[cloud])[idx];
    for (int idx = t; idx < NODES; idx += 256)
        sadj[idx] = g_adj[cloud][i][idx];
    __syncthreads();

    if (t < 64) {
        int    a  = t >> 3, bb = t & 7;
        double acc = 0.0;
        int    deg = 0;
        for (int k = 0; k < NODES; k++) {
            if (!sadj[k]) continue;
            deg++;
            if (k < i) {
                double d[S];
                double dn2 = 0.0;
                #pragma unroll
                for (int c = 0; c < S; c++) {
                    d[c] = (double)sX[i][c] - (double)sX[k][c];
                    dn2 += d[c] * d[c];
                }
                double dn    = sqrt(dn2) + 1e-12;
                double alpha = fmin(dn, 1.0);
                double coef  = (2.0 * alpha - alpha * alpha) / (dn * dn);
                acc -= coef * d[a] * d[bb];
            }
        }
        if (a == bb) acc += (double)deg;
        sdiag[t] = acc;
    }
    __syncthreads();

    int   a    = t >> 5;
    int   lane = t & 31;
    float2* rowp = g_A[cloud] + (size_t)(8 * i + a) * NN;
    for (int cb = 0; cb < NN; cb += 32) {
        int col = cb + lane;
        int j   = col >> 3, bb = col & 7;
        double val = 0.0;
        if (j == i) {
            val = sdiag[a * 8 + bb];
        } else if (sadj[j]) {
            double d[S];
            double dn2 = 0.0;
            #pragma unroll
            for (int c = 0; c < S; c++) {
                d[c] = (double)sX[j][c] - (double)sX[i][c];
                dn2 += d[c] * d[c];
            }
            double dn    = sqrt(dn2) + 1e-12;
            double alpha = fmin(dn, 1.0);
            double sc    = alpha / (dn * dn);
            val = sc * d[a] * d[bb] - (a == bb ? 1.0 : 0.0);
        }
        float hi = (float)val;
        float lo = (float)(val - (double)hi);
        rowp[col] = make_float2(hi, lo);
    }
}

/* ------------------------------------------------------------------ */
/* K4: persistent blocked (latrd P=8) mixed-precision tridiagonalize    */
/* ------------------------------------------------------------------ */
__global__ __launch_bounds__(TPB, 2) void k_tridiag()
{
    extern __shared__ float fsm[];
    float* sv  = fsm;                 /* pass B: v (<= NN floats)    */
    float* sVc = fsm;                 /* RMW alias  [PW][CW]         */
    float* sWc = fsm + PW * CW;       /* RMW alias  [PW][CW]         */

    __shared__ double sred[TPB / 32];
    __shared__ float  scoefA[PW], scoefB[PW];
    __shared__ double stau[PW], sc2[PW];
    __shared__ double sD1[PW], sD2[PW];

    int mat  = blockIdx.x / NB;
    int blk  = blockIdx.x % NB;
    int tid  = threadIdx.x;
    int lane = tid & 31;
    int wid  = tid >> 5;
    int gw   = blk * (TPB / 32) + wid;
    float2* A = g_A[mat];

    for (int idx = blk * TPB + tid; idx < NN; idx += NB * TPB) {
        g_nrm[mat][idx] = 0.0;
        g_vt[mat][idx]  = 0.0;
    }
    for (int idx = blk * TPB + tid; idx < NN * PW; idx += NB * TPB) {
        ((double*)g_d1[mat])[idx] = 0.0;
        ((double*)g_d2[mat])[idx] = 0.0;
    }
    gridbar(mat);

    for (int k0 = 0; k0 < NN - 2; k0 += PW) {
        int Pn = NN - 2 - k0; if (Pn > PW) Pn = PW;

        for (int i = 0; i < Pn; ++i) {
            int j = k0 + i, m = NN - 1 - j, base = j + 1;

            /* ---- pass A: candidate column + norm + panel dot raws ---- */
            if (tid == 0) {
                for (int p = 0; p < i; p++) {
                    double tp, bp, sp;
                    refl(mat, k0 + p, tp, bp, sp);
                    double cp = 0.5 * tp * tp * g_vt[mat][k0 + p];
                    stau[p] = tp; sc2[p] = cp;
                    double vpj = (double)g_V[mat][p][j];
                    double ypj = (double)g_Yp[mat][p][j];
                    double wpj = tp * ypj - cp * vpj;
                    scoefA[p] = (float)(vpj * tp);
                    scoefB[p] = (float)(wpj - vpj * cp);
                }
            }
            __syncthreads();

            int q = blk * TPB + tid;
            double nrmp = 0.0;
            float d1p[PW], d2p[PW];
            #pragma unroll
            for (int p = 0; p < PW; p++) { d1p[p] = 0.f; d2p[p] = 0.f; }

            if (q < m) {
                int c = base + q;
                float2 a = A[(size_t)j * NN + c];
                float cand = __fadd_rn(a.x, a.y);
                #pragma unroll
                for (int p = 0; p < PW; p++) if (p < i) {
                    float V_ = g_V[mat][p][c], Y_ = g_Yp[mat][p][c];
                    cand = __fsub_rn(cand,
                        __fmaf_rn(scoefA[p], Y_, __fmul_rn(scoefB[p], V_)));
                }
                g_cand[mat][q] = cand;
                if (q == 0) {
                    g_alf[mat][j] = (double)cand;
                } else {
                    nrmp = (double)cand * (double)cand;
                    #pragma unroll
                    for (int p = 0; p < PW; p++) if (p < i) {
                        float V_ = g_V[mat][p][c], Y_ = g_Yp[mat][p][c];
                        float W_ = __fmaf_rn((float)stau[p], Y_,
                                             -(float)sc2[p] * V_);
                        d1p[p] = __fmul_rn(cand, W_);
                        d2p[p] = __fmul_rn(cand, V_);
                    }
                }
            }
            #pragma unroll
            for (int o = 16; o; o >>= 1) nrmp += __shfl_xor_sync(~0u, nrmp, o);
            if (lane == 0 && nrmp != 0.0) atomicAdd(&g_nrm[mat][j], nrmp);
            #pragma unroll
            for (int p = 0; p < PW; p++) {
                float v1 = d1p[p], v2 = d2p[p];
                #pragma unroll
                for (int o = 16; o; o >>= 1) {
                    v1 += __shfl_xor_sync(~0u, v1, o);
                    v2 += __shfl_xor_sync(~0u, v2, o);
                }
                if (lane == 0 && p < i) {
                    if (v1 != 0.f) atomicAdd(&g_d1[mat][j][p], (double)v1);
                    if (v2 != 0.f) atomicAdd(&g_d2[mat][j][p], (double)v2);
                }
            }
            if (blk == 0 && tid == TPB - 1) {
                float2 a = A[(size_t)j * NN + j];
                double dg = (double)a.x + (double)a.y;
                for (int p = 0; p < i; p++) {
                    double vj = (double)g_V[mat][p][j];
                    double yj = (double)g_Yp[mat][p][j];
                    dg -= 2.0 * vj * (stau[p] * yj - sc2[p] * vj);
                }
                g_diag[mat][j] = dg;
            }
            gridbar(mat);

            /* ---- pass B: read-only SYMV + corrections + vty ---- */
            double tau, beta, scale;
            refl(mat, j, tau, beta, scale);
            if (blk == 0 && tid == 0) g_offd[mat][j] = beta;

            for (int t = tid; t < m; t += TPB)
                sv[t] = (t == 0) ? 1.0f
                                 : (float)((double)g_cand[mat][t] * scale);
            if (tid == 0) {
                for (int p = 0; p < i; p++) {
                    double vb = (double)g_V[mat][p][base];
                    double yb = (double)g_Yp[mat][p][base];
                    double wb = stau[p] * yb - sc2[p] * vb;
                    sD1[p] = wb + scale * g_d1[mat][j][p];
                    sD2[p] = vb + scale * g_d2[mat][j][p];
                }
            }
            __syncthreads();
            for (int t = blk * TPB + tid; t < m; t += NB * TPB)
                g_V[mat][i][base + t] = sv[t];

            double vtyp = 0.0;
            for (int qq = gw; qq < m; qq += NWT) {
                int r = base + qq;
                const float2* Ar = A + (size_t)r * NN + base;
                float s0 = 0.f, c0 = 0.f, s1 = 0.f, c1 = 0.f;
                int t = lane;
                for (; t + 32 < m; t += 64) {
                    float2 a = Ar[t];
                    float2 b = Ar[t + 32];
                    float p0 = __fmaf_rn(a.y, sv[t],      __fmul_rn(a.x, sv[t]));
                    float p1 = __fmaf_rn(b.y, sv[t + 32], __fmul_rn(b.x, sv[t + 32]));
                    KH(s0, c0, p0);
                    KH(s1, c1, p1);
                }
                for (; t < m; t += 32) {
                    float2 a = Ar[t];
                    float p0 = __fmaf_rn(a.y, sv[t], __fmul_rn(a.x, sv[t]));
                    KH(s0, c0, p0);
                }
                double y = ((double)s0 + (double)c0) + ((double)s1 + (double)c1);
                #pragma unroll
                for (int o = 16; o; o >>= 1) y += __shfl_xor_sync(~0u, y, o);
                if (lane == 0) {
                    for (int p = 0; p < i; p++) {
                        double Vr = (double)g_V[mat][p][r];
                        double Yr = (double)g_Yp[mat][p][r];
                        double Wr = stau[p] * Yr - sc2[p] * Vr;
                        y -= Vr * sD1[p] + Wr * sD2[p];
                    }
                    g_Yp[mat][i][r] = (float)y;
                    vtyp += (double)sv[qq] * y;
                }
            }
            if (lane == 0) sred[wid] = vtyp;
            __syncthreads();
            if (tid == 0) {
                double s = 0.0;
                for (int w = 0; w < TPB / 32; w++) s += sred[w];
                if (s != 0.0) atomicAdd(&g_vt[mat][j], s);
            }
            gridbar(mat);
        }

        /* ---- panel rank-2P EFT RMW of trailing block ---- */
        {
            int base2 = k0 + Pn;
            int mrem  = NN - base2;
            if (tid == 0) {
                for (int p = 0; p < Pn; p++) {
                    double tp, bp, sp;
                    refl(mat, k0 + p, tp, bp, sp);
                    stau[p] = tp;
                    sc2[p]  = 0.5 * tp * tp * g_vt[mat][k0 + p];
                }
            }
            __syncthreads();
            for (int cc = 0; cc < mrem; cc += CW) {
                int cw = mrem - cc; if (cw > CW) cw = CW;
                __syncthreads();
                for (int p = 0; p < Pn; p++) {
                    float tpf = (float)stau[p], cpf = (float)sc2[p];
                    for (int idx = tid; idx < cw; idx += TPB) {
                        int c = base2 + cc + idx;
                        float V_ = g_V[mat][p][c], Y_ = g_Yp[mat][p][c];
                        sVc[p * CW + idx] = V_;
                        sWc[p * CW + idx] = __fmaf_rn(tpf, Y_, -cpf * V_);
                    }
                }
                __syncthreads();
                for (int qq = gw; qq < mrem; qq += NWT) {
                    int r = base2 + qq;
                    float Vr[PW], Wr[PW];
                    #pragma unroll
                    for (int p = 0; p < PW; p++) {
                        if (p < Pn) {
                            float v_ = g_V[mat][p][r], y_ = g_Yp[mat][p][r];
                            Vr[p] = v_;
                            Wr[p] = __fmaf_rn((float)stau[p], y_,
                                              -(float)sc2[p] * v_);
                        } else { Vr[p] = 0.f; Wr[p] = 0.f; }
                    }
                    float2* Ar = A + (size_t)r * NN + (base2 + cc);
                    for (int t = lane; t < cw; t += 32) {
                        float2 a = Ar[t];
                        float dl = 0.f;
                        #pragma unroll
                        for (int p = 0; p < PW; p++) if (p < Pn)
                            dl = __fmaf_rn(-Vr[p], sWc[p * CW + t],
                                 __fmaf_rn(-Wr[p], sVc[p * CW + t], dl));
                        float d2 = __fadd_rn(dl, a.y);
                        float hi = __fadd_rn(a.x, d2);
                        float bp = __fsub_rn(hi, a.x);
                        float ap = __fsub_rn(hi, bp);
                        float lo = __fadd_rn(__fsub_rn(a.x, ap),
                                             __fsub_rn(d2, bp));
                        Ar[t] = make_float2(hi, lo);
                    }
                }
            }
            gridbar(mat);
        }
    }

    /* tail */
    if (blk == 0 && tid == 0) {
        float2 a = A[(size_t)(NN - 2) * NN + (NN - 2)];
        g_diag[mat][NN - 2] = (double)a.x + (double)a.y;
        a = A[(size_t)(NN - 1) * NN + (NN - 1)];
        g_diag[mat][NN - 1] = (double)a.x + (double)a.y;
        a = A[(size_t)(NN - 2) * NN + (NN - 1)];
        g_offd[mat][NN - 2] = (double)a.x + (double)a.y;
        g_offd[mat][NN - 1] = 0.0;
    }
}

/* ------------------------------------------------------------------ */
__global__ __launch_bounds__(256) void k_bisect()
{
    int mat = blockIdx.y;
    __shared__ float sa[NN];
    __shared__ float sb2[NN];
    __shared__ float red[256];
    __shared__ float s_gl, s_gu, s_pm;
    int t = threadIdx.x;
    for (int i = t; i < NN; i += 256) {
        sa[i] = (float)g_diag[mat][i];
        float b = (i < NN - 1) ? (float)g_offd[mat][i] : 0.f;
        sb2[i] = b * b;
    }
    __syncthreads();

    float lo = 3.4e38f, hi = -3.4e38f, mb2 = 0.f;
    for (int i = t; i < NN; i += 256) {
        float bl = (i > 0)      ? sqrtf(sb2[i - 1]) : 0.f;
        float br = (i < NN - 1) ? sqrtf(sb2[i])     : 0.f;
        lo  = fminf(lo, sa[i] - bl - br);
        hi  = fmaxf(hi, sa[i] + bl + br);
        mb2 = fmaxf(mb2, sb2[i]);
    }
    red[t] = lo;  __syncthreads();
    for (int off = 128; off; off >>= 1) { if (t < off) red[t] = fminf(red[t], red[t + off]); __syncthreads(); }
    if (t == 0) s_gl = red[0];
    __syncthreads();
    red[t] = hi;  __syncthreads();
    for (int off = 128; off; off >>= 1) { if (t < off) red[t] = fmaxf(red[t], red[t + off]); __syncthreads(); }
    if (t == 0) s_gu = red[0];
    __syncthreads();
    red[t] = mb2; __syncthreads();
    for (int off = 128; off; off >>= 1) { if (t < off) red[t] = fmaxf(red[t], red[t + off]); __syncthreads(); }
    if (t == 0) s_pm = red[0];
    __syncthreads();

    float span   = s_gu - s_gl;
    float gl     = s_gl - 0.01f * span - 1e-3f;
    float gu     = s_gu + 0.01f * span + 1e-3f;
    float pivmin = fmaxf(s_pm * 1.2e-38f, 1.2e-38f);

    int tgt = blockIdx.x * 256 + t;
    float blo = gl, bhi = gu;
    for (int it = 0; it < 32; it++) {
        float mid = 0.5f * (blo + bhi);
        if (mid <= blo || mid >= bhi) break;
        float d   = sa[0] - mid;
        int   cnt = (d < 0.f);
        #pragma unroll 8
        for (int i = 1; i < NN; i++) {
            d = (sa[i] - mid) - __fdividef(sb2[i - 1], d);
            if (fabsf(d) < pivmin) d = -pivmin;
            cnt += (d < 0.f);
        }
        if (cnt > tgt) bhi = mid; else blo = mid;
    }
    g_eig[mat][tgt] = 0.5f * (blo + bhi);
}

/* ------------------------------------------------------------------ */
__global__ __launch_bounds__(256) void k_final(float* __restrict__ out)
{
    __shared__ double sn[256], sd_[256];
    double gap[2];
    int t = threadIdx.x;
    for (int mat = 0; mat < 2; mat++) {
        double accn = 0.0, accd = 0.0;
        for (int i = t; i < NN; i += 256) {
            double lam = (double)fmaxf(g_eig[mat][i], 0.f);
            double z   = (lam - 1e-4) / 0.01;
            double s   = 1.0 / (1.0 + exp(-z));
            accn += lam * s;
            accd += s;
        }
        sn[t] = accn; sd_[t] = accd;
        __syncthreads();
        for (int off = 128; off; off >>= 1) {
            if (t < off) { sn[t] += sn[t + off]; sd_[t] += sd_[t + off]; }
            __syncthreads();
        }
        gap[mat] = sn[0] / (sd_[0] + 1e-12);
        __syncthreads();
    }
    if (t == 0) {
        double trip = gap[0] - gap[1] + 0.5;
        if (trip < 0.0) trip = 0.0;
        out[0] = (float)(trip + 0.1 * gap[0]);
    }
}

/* ------------------------------------------------------------------ */
extern "C" void kernel_launch(void* const* d_in, const int* in_sizes, int n_in,
                              void* d_out, int out_size)
{
    const float* q   = (const float*)d_in[0];
    const float* pos = (const float*)d_in[1];
    const float* neg = (const float*)d_in[2];
    const float* W   = (const float*)d_in[3];
    (void)in_sizes; (void)n_in; (void)out_size;

    int smem = 2 * PW * CW * (int)sizeof(float);   /* 64 KB */
    cudaFuncSetAttribute((const void*)k_tridiag,
                         cudaFuncAttributeMaxDynamicSharedMemorySize, smem);

    k_proj<<<1024, 256>>>(q, pos, neg, W);
    k_knn<<<1024, 256>>>();
    {
        dim3 ga(512, 2);
        k_assemble<<<ga, 256>>>();
    }
    k_tridiag<<<2 * NB, TPB, smem>>>();
    {
        dim3 gb(16, 2);
        k_bisect<<<gb, 256>>>();
    }
    k_final<<<1, 256>>>((float*)d_out);
}

// round 11
// speedup vs baseline: 1.1226x; 1.1226x over previous
#include <cuda_runtime.h>
#include <math.h>

#define NODES 512
#define S     8
#define DIN   768
#define NN    4096
#define NB    148                  /* persistent blocks per matrix */
#define TPB   512
#define NWT   (NB * (TPB / 32))    /* warps per matrix = 2368 */
#define PW    8                    /* panel width */
#define CW    1024                 /* RMW column chunk */

#define KH(s, c, p) do {                                 \
    float _y = __fsub_rn((p), (c));                      \
    float _t = __fadd_rn((s), _y);                       \
    (c) = __fsub_rn(__fsub_rn(_t, (s)), _y);             \
    (s) = _t;                                            \
} while (0)

/* ------------------------------------------------------------------ */
__device__ float         g_X[2][NODES][S];
__device__ unsigned char g_adj[2][NODES][NODES];
__device__ __align__(16) float g_Ah[2][(size_t)NN * NN];  /* hi plane */
__device__ __align__(16) float g_Al[2][(size_t)NN * NN];  /* lo plane */
__device__ float         g_V[2][PW][NN];
__device__ float         g_Yp[2][PW][NN];
__device__ float         g_cand[2][NN];
__device__ double        g_nrm[2][NN];
__device__ double        g_alf[2][NN];
__device__ double        g_vt[2][NN];
__device__ double        g_d1[2][NN][PW];
__device__ double        g_d2[2][NN][PW];
__device__ double        g_diag[2][NN];
__device__ double        g_offd[2][NN];
__device__ float         g_eig[2][NN];
__device__ unsigned int  g_count[2];
__device__ unsigned int  g_gen[2];

/* ------------------------------------------------------------------ */
__device__ __forceinline__ void gridbar(int mat)
{
    __threadfence();
    __syncthreads();
    if (threadIdx.x == 0) {
        volatile unsigned int* genp = &g_gen[mat];
        unsigned int old = *genp;
        if (atomicAdd(&g_count[mat], 1u) == (unsigned)(NB - 1)) {
            atomicExch(&g_count[mat], 0u);
            __threadfence();
            atomicExch(&g_gen[mat], old + 1u);
        } else {
            while (*genp == old) __nanosleep(64);
        }
        __threadfence();
    }
    __syncthreads();
}

__device__ __forceinline__ void refl(int mat, int j,
                                     double& tau, double& beta, double& scale)
{
    double n = g_nrm[mat][j], a = g_alf[mat][j];
    if (n == 0.0) { tau = 0.0; beta = a; scale = 0.0; }
    else {
        beta  = -copysign(sqrt(a * a + n), a);
        tau   = (beta - a) / beta;
        scale = 1.0 / (a - beta);
    }
}

/* ------------------------------------------------------------------ */
__global__ __launch_bounds__(256) void k_proj(const float* __restrict__ q,
                                              const float* __restrict__ pos,
                                              const float* __restrict__ neg,
                                              const float* __restrict__ W)
{
    int b     = blockIdx.x;
    int cloud = b >> 9;
    int row   = b & 511;
    const float* src = (row < 256) ? (q + (size_t)row * DIN)
                                   : ((cloud == 0 ? pos : neg) + (size_t)(row - 256) * DIN);
    __shared__ float sm[256];
    int t = threadIdx.x;
    int c = t & 7;
    int g = t >> 3;
    float acc = 0.f;
    for (int j = g; j < DIN; j += 32)
        acc += src[j] * W[c * DIN + j];
    sm[t] = acc;
    __syncthreads();
    for (int off = 128; off >= 8; off >>= 1) {
        if (t < off) sm[t] += sm[t + off];
        __syncthreads();
    }
    if (t < 8) g_X[cloud][row][t] = sm[t];

    int* adj32 = (int*)g_adj;
    int  base  = b * 128;
    for (int i = t; i < 128; i += 256) adj32[base + i] = 0;
}

/* ------------------------------------------------------------------ */
__global__ __launch_bounds__(256) void k_knn()
{
    int b     = blockIdx.x;
    int cloud = b >> 9;
    int i     = b & 511;
    __shared__ float sX[NODES][S];
    __shared__ float sd[NODES];
    int t = threadIdx.x;
    for (int idx = t; idx < NODES * S; idx += 256)
        ((float*)sX)[idx] = ((const float*)g_X[cloud])[idx];
    __syncthreads();
    for (int j = t; j < NODES; j += 256) {
        float d2 = 0.f;
        #pragma unroll
        for (int c = 0; c < S; c++) {
            float d = sX[j][c] - sX[i][c];
            d2 += d * d;
        }
        sd[j] = (j == i) ? 3.4e38f : d2;
    }
    __syncthreads();
    if (t == 0) {
        for (int p = 0; p < 5; p++) {
            float best = 3.4e38f;
            int   bj   = 0;
            for (int j = 0; j < NODES; j++)
                if (sd[j] < best) { best = sd[j]; bj = j; }
            sd[bj] = 3.4e38f;
            g_adj[cloud][i][bj] = 1;
            g_adj[cloud][bj][i] = 1;
        }
    }
}

/* ------------------------------------------------------------------ */
__global__ __launch_bounds__(256) void k_assemble()
{
    int i     = blockIdx.x;
    int cloud = blockIdx.y;
    __shared__ float         sX[NODES][S];
    __shared__ unsigned char sadj[NODES];
    __shared__ double        sdiag[64];
    int t = threadIdx.x;
    for (int idx = t; idx < NODES * S; idx += 256)
        ((float*)sX)[idx] = ((const float*)g_X[cloud])[idx];
    for (int idx = t; idx < NODES; idx += 256)
        sadj[idx] = g_adj[cloud][i][idx];
    __syncthreads();

    if (t < 64) {
        int    a  = t >> 3, bb = t & 7;
        double acc = 0.0;
        int    deg = 0;
        for (int k = 0; k < NODES; k++) {
            if (!sadj[k]) continue;
            deg++;
            if (k < i) {
                double d[S];
                double dn2 = 0.0;
                #pragma unroll
                for (int c = 0; c < S; c++) {
                    d[c] = (double)sX[i][c] - (double)sX[k][c];
                    dn2 += d[c] * d[c];
                }
                double dn    = sqrt(dn2) + 1e-12;
                double alpha = fmin(dn, 1.0);
                double coef  = (2.0 * alpha - alpha * alpha) / (dn * dn);
                acc -= coef * d[a] * d[bb];
            }
        }
        if (a == bb) acc += (double)deg;
        sdiag[t] = acc;
    }
    __syncthreads();

    int   a    = t >> 5;
    int   lane = t & 31;
    size_t rowoff = (size_t)(8 * i + a) * NN;
    for (int cb = 0; cb < NN; cb += 32) {
        int col = cb + lane;
        int j   = col >> 3, bb = col & 7;
        double val = 0.0;
        if (j == i) {
            val = sdiag[a * 8 + bb];
        } else if (sadj[j]) {
            double d[S];
            double dn2 = 0.0;
            #pragma unroll
            for (int c = 0; c < S; c++) {
                d[c] = (double)sX[j][c] - (double)sX[i][c];
                dn2 += d[c] * d[c];
            }
            double dn    = sqrt(dn2) + 1e-12;
            double alpha = fmin(dn, 1.0);
            double sc    = alpha / (dn * dn);
            val = sc * d[a] * d[bb] - (a == bb ? 1.0 : 0.0);
        }
        float hi = (float)val;
        float lo = (float)(val - (double)hi);
        g_Ah[cloud][rowoff + col] = hi;
        g_Al[cloud][rowoff + col] = lo;
    }
}

/* ------------------------------------------------------------------ */
/* K4: persistent blocked (latrd P=8) mixed-precision tridiagonalize    */
/* hi/lo split planes: SYMV reads hi only (4 B/elem), RMW updates both. */
/* ------------------------------------------------------------------ */
__global__ __launch_bounds__(TPB, 2) void k_tridiag()
{
    extern __shared__ float fsm[];
    float* sv  = fsm;                 /* pass B: v (<= NN floats)    */
    float* sVc = fsm;                 /* RMW alias  [PW][CW]         */
    float* sWc = fsm + PW * CW;       /* RMW alias  [PW][CW]         */

    __shared__ double sred[TPB / 32];
    __shared__ float  scoefA[PW], scoefB[PW];
    __shared__ double stau[PW], sc2[PW];
    __shared__ double sD1[PW], sD2[PW];

    int mat  = blockIdx.x / NB;
    int blk  = blockIdx.x % NB;
    int tid  = threadIdx.x;
    int lane = tid & 31;
    int wid  = tid >> 5;
    int gw   = blk * (TPB / 32) + wid;
    float* Ah = g_Ah[mat];
    float* Al = g_Al[mat];

    for (int idx = blk * TPB + tid; idx < NN; idx += NB * TPB) {
        g_nrm[mat][idx] = 0.0;
        g_vt[mat][idx]  = 0.0;
    }
    for (int idx = blk * TPB + tid; idx < NN * PW; idx += NB * TPB) {
        ((double*)g_d1[mat])[idx] = 0.0;
        ((double*)g_d2[mat])[idx] = 0.0;
    }
    gridbar(mat);

    for (int k0 = 0; k0 < NN - 2; k0 += PW) {
        int Pn = NN - 2 - k0; if (Pn > PW) Pn = PW;

        for (int i = 0; i < Pn; ++i) {
            int j = k0 + i, m = NN - 1 - j, base = j + 1;

            /* ---- pass A: candidate column + norm + panel dot raws ---- */
            if (tid == 0) {
                for (int p = 0; p < i; p++) {
                    double tp, bp, sp;
                    refl(mat, k0 + p, tp, bp, sp);
                    double cp = 0.5 * tp * tp * g_vt[mat][k0 + p];
                    stau[p] = tp; sc2[p] = cp;
                    double vpj = (double)g_V[mat][p][j];
                    double ypj = (double)g_Yp[mat][p][j];
                    double wpj = tp * ypj - cp * vpj;
                    scoefA[p] = (float)(vpj * tp);
                    scoefB[p] = (float)(wpj - vpj * cp);
                }
            }
            __syncthreads();

            int q = blk * TPB + tid;
            double nrmp = 0.0;
            float d1p[PW], d2p[PW];
            #pragma unroll
            for (int p = 0; p < PW; p++) { d1p[p] = 0.f; d2p[p] = 0.f; }

            if (q < m) {
                int c = base + q;
                float cand = Ah[(size_t)j * NN + c];
                #pragma unroll
                for (int p = 0; p < PW; p++) if (p < i) {
                    float V_ = g_V[mat][p][c], Y_ = g_Yp[mat][p][c];
                    cand = __fsub_rn(cand,
                        __fmaf_rn(scoefA[p], Y_, __fmul_rn(scoefB[p], V_)));
                }
                g_cand[mat][q] = cand;
                if (q == 0) {
                    g_alf[mat][j] = (double)cand;
                } else {
                    nrmp = (double)cand * (double)cand;
                    #pragma unroll
                    for (int p = 0; p < PW; p++) if (p < i) {
                        float V_ = g_V[mat][p][c], Y_ = g_Yp[mat][p][c];
                        float W_ = __fmaf_rn((float)stau[p], Y_,
                                             -(float)sc2[p] * V_);
                        d1p[p] = __fmul_rn(cand, W_);
                        d2p[p] = __fmul_rn(cand, V_);
                    }
                }
            }
            #pragma unroll
            for (int o = 16; o; o >>= 1) nrmp += __shfl_xor_sync(~0u, nrmp, o);
            if (lane == 0 && nrmp != 0.0) atomicAdd(&g_nrm[mat][j], nrmp);
            #pragma unroll
            for (int p = 0; p < PW; p++) {
                float v1 = d1p[p], v2 = d2p[p];
                #pragma unroll
                for (int o = 16; o; o >>= 1) {
                    v1 += __shfl_xor_sync(~0u, v1, o);
                    v2 += __shfl_xor_sync(~0u, v2, o);
                }
                if (lane == 0 && p < i) {
                    if (v1 != 0.f) atomicAdd(&g_d1[mat][j][p], (double)v1);
                    if (v2 != 0.f) atomicAdd(&g_d2[mat][j][p], (double)v2);
                }
            }
            if (blk == 0 && tid == TPB - 1) {
                double dg = (double)Ah[(size_t)j * NN + j]
                          + (double)Al[(size_t)j * NN + j];
                for (int p = 0; p < i; p++) {
                    double vj = (double)g_V[mat][p][j];
                    double yj = (double)g_Yp[mat][p][j];
                    dg -= 2.0 * vj * (stau[p] * yj - sc2[p] * vj);
                }
                g_diag[mat][j] = dg;
            }
            gridbar(mat);

            /* ---- pass B: hi-only float4 SYMV (2 rows/warp) + vty ---- */
            double tau, beta, scale;
            refl(mat, j, tau, beta, scale);
            if (blk == 0 && tid == 0) g_offd[mat][j] = beta;

            for (int t = tid; t < m; t += TPB)
                sv[t] = (t == 0) ? 1.0f
                                 : (float)((double)g_cand[mat][t] * scale);
            if (tid == 0) {
                for (int p = 0; p < i; p++) {
                    double vb = (double)g_V[mat][p][base];
                    double yb = (double)g_Yp[mat][p][base];
                    double wb = stau[p] * yb - sc2[p] * vb;
                    sD1[p] = wb + scale * g_d1[mat][j][p];
                    sD2[p] = vb + scale * g_d2[mat][j][p];
                }
            }
            __syncthreads();
            for (int t = blk * TPB + tid; t < m; t += NB * TPB)
                g_V[mat][i][base + t] = sv[t];

            int peel = (4 - (base & 3)) & 3; if (peel > m) peel = m;
            int NP   = (m - peel) >> 2;
            int remb = peel + 4 * NP;        /* tail starts here */

            double vtyp = 0.0;
            int q1 = gw;
            if (q1 < m) {
                int  q2 = q1 + NWT;
                bool r2 = (q2 < m);
                const float*  Ar1 = Ah + (size_t)(base + q1) * NN + base;
                const float4* A41 = (const float4*)(Ar1 + peel);
                const float*  Ar2 = r2 ? (Ah + (size_t)(base + q2) * NN + base) : Ar1;
                const float4* A42 = (const float4*)(Ar2 + peel);

                float s10 = 0.f, c10 = 0.f, s11 = 0.f, c11 = 0.f;
                float s20 = 0.f, c20 = 0.f, s21 = 0.f, c21 = 0.f;

                if (lane == 0) {
                    for (int t = 0; t < peel; t++) {
                        float vt_ = sv[t];
                        float p1 = __fmul_rn(Ar1[t], vt_);
                        KH(s10, c10, p1);
                        if (r2) { float p2 = __fmul_rn(Ar2[t], vt_); KH(s20, c20, p2); }
                    }
                    for (int t = remb; t < m; t++) {
                        float vt_ = sv[t];
                        float p1 = __fmul_rn(Ar1[t], vt_);
                        KH(s11, c11, p1);
                        if (r2) { float p2 = __fmul_rn(Ar2[t], vt_); KH(s21, c21, p2); }
                    }
                }
                if (r2) {
                    for (int k = lane; k < NP; k += 32) {
                        int tt = peel + 4 * k;
                        float v0 = sv[tt], v1 = sv[tt + 1],
                              v2 = sv[tt + 2], v3 = sv[tt + 3];
                        float4 a = A41[k];
                        float4 b = A42[k];
                        float pa0 = __fmaf_rn(a.y, v1, __fmul_rn(a.x, v0));
                        float pa1 = __fmaf_rn(a.w, v3, __fmul_rn(a.z, v2));
                        float pb0 = __fmaf_rn(b.y, v1, __fmul_rn(b.x, v0));
                        float pb1 = __fmaf_rn(b.w, v3, __fmul_rn(b.z, v2));
                        KH(s10, c10, pa0);
                        KH(s11, c11, pa1);
                        KH(s20, c20, pb0);
                        KH(s21, c21, pb1);
                    }
                } else {
                    #pragma unroll 2
                    for (int k = lane; k < NP; k += 32) {
                        int tt = peel + 4 * k;
                        float4 a = A41[k];
                        float pa0 = __fmaf_rn(a.y, sv[tt + 1], __fmul_rn(a.x, sv[tt]));
                        float pa1 = __fmaf_rn(a.w, sv[tt + 3], __fmul_rn(a.z, sv[tt + 2]));
                        KH(s10, c10, pa0);
                        KH(s11, c11, pa1);
                    }
                }

                double y1 = ((double)s10 + (double)c10) + ((double)s11 + (double)c11);
                #pragma unroll
                for (int o = 16; o; o >>= 1) y1 += __shfl_xor_sync(~0u, y1, o);
                if (lane == 0) {
                    int r = base + q1;
                    for (int p = 0; p < i; p++) {
                        double Vr = (double)g_V[mat][p][r];
                        double Yr = (double)g_Yp[mat][p][r];
                        double Wr = stau[p] * Yr - sc2[p] * Vr;
                        y1 -= Vr * sD1[p] + Wr * sD2[p];
                    }
                    g_Yp[mat][i][r] = (float)y1;
                    vtyp += (double)sv[q1] * y1;
                }
                if (r2) {
                    double y2 = ((double)s20 + (double)c20) + ((double)s21 + (double)c21);
                    #pragma unroll
                    for (int o = 16; o; o >>= 1) y2 += __shfl_xor_sync(~0u, y2, o);
                    if (lane == 0) {
                        int r = base + q2;
                        for (int p = 0; p < i; p++) {
                            double Vr = (double)g_V[mat][p][r];
                            double Yr = (double)g_Yp[mat][p][r];
                            double Wr = stau[p] * Yr - sc2[p] * Vr;
                            y2 -= Vr * sD1[p] + Wr * sD2[p];
                        }
                        g_Yp[mat][i][r] = (float)y2;
                        vtyp += (double)sv[q2] * y2;
                    }
                }
            }
            if (lane == 0) sred[wid] = vtyp;
            __syncthreads();
            if (tid == 0) {
                double s = 0.0;
                for (int w = 0; w < TPB / 32; w++) s += sred[w];
                if (s != 0.0) atomicAdd(&g_vt[mat][j], s);
            }
            gridbar(mat);
        }

        /* ---- panel rank-2P EFT RMW (float4 on both planes) ---- */
        {
            int base2 = k0 + Pn;          /* multiple of 8 while Pn==PW */
            int mrem  = NN - base2;
            if (tid == 0) {
                for (int p = 0; p < Pn; p++) {
                    double tp, bp, sp;
                    refl(mat, k0 + p, tp, bp, sp);
                    stau[p] = tp;
                    sc2[p]  = 0.5 * tp * tp * g_vt[mat][k0 + p];
                }
            }
            __syncthreads();
            for (int cc = 0; cc < mrem; cc += CW) {
                int cw = mrem - cc; if (cw > CW) cw = CW;
                __syncthreads();
                for (int p = 0; p < Pn; p++) {
                    float tpf = (float)stau[p], cpf = (float)sc2[p];
                    for (int idx = tid; idx < cw; idx += TPB) {
                        int c = base2 + cc + idx;
                        float V_ = g_V[mat][p][c], Y_ = g_Yp[mat][p][c];
                        sVc[p * CW + idx] = V_;
                        sWc[p * CW + idx] = __fmaf_rn(tpf, Y_, -cpf * V_);
                    }
                }
                __syncthreads();
                int cw4 = cw >> 2;        /* cw is a multiple of 8 */
                for (int qq = gw; qq < mrem; qq += NWT) {
                    int r = base2 + qq;
                    float Vr[PW], Wr[PW];
                    #pragma unroll
                    for (int p = 0; p < PW; p++) {
                        if (p < Pn) {
                            float v_ = g_V[mat][p][r], y_ = g_Yp[mat][p][r];
                            Vr[p] = v_;
                            Wr[p] = __fmaf_rn((float)stau[p], y_,
                                              -(float)sc2[p] * v_);
                        } else { Vr[p] = 0.f; Wr[p] = 0.f; }
                    }
                    float4* Ah4 = (float4*)(Ah + (size_t)r * NN + base2 + cc);
                    float4* Al4 = (float4*)(Al + (size_t)r * NN + base2 + cc);
                    for (int t4 = lane; t4 < cw4; t4 += 32) {
                        float4 h = Ah4[t4];
                        float4 l = Al4[t4];
                        int tb = 4 * t4;
                        float dl0 = 0.f, dl1 = 0.f, dl2 = 0.f, dl3 = 0.f;
                        #pragma unroll
                        for (int p = 0; p < PW; p++) if (p < Pn) {
                            const float* Vp = sVc + p * CW + tb;
                            const float* Wp = sWc + p * CW + tb;
                            dl0 = __fmaf_rn(-Vr[p], Wp[0], __fmaf_rn(-Wr[p], Vp[0], dl0));
                            dl1 = __fmaf_rn(-Vr[p], Wp[1], __fmaf_rn(-Wr[p], Vp[1], dl1));
                            dl2 = __fmaf_rn(-Vr[p], Wp[2], __fmaf_rn(-Wr[p], Vp[2], dl2));
                            dl3 = __fmaf_rn(-Vr[p], Wp[3], __fmaf_rn(-Wr[p], Vp[3], dl3));
                        }
#define TS(HX, LX, DL) do {                                        \
    float _d2 = __fadd_rn((DL), (LX));                             \
    float _hi = __fadd_rn((HX), _d2);                              \
    float _bp = __fsub_rn(_hi, (HX));                              \
    float _ap = __fsub_rn(_hi, _bp);                               \
    (LX) = __fadd_rn(__fsub_rn((HX), _ap), __fsub_rn(_d2, _bp));   \
    (HX) = _hi;                                                    \
} while (0)
                        TS(h.x, l.x, dl0);
                        TS(h.y, l.y, dl1);
                        TS(h.z, l.z, dl2);
                        TS(h.w, l.w, dl3);
#undef TS
                        Ah4[t4] = h;
                        Al4[t4] = l;
                    }
                }
            }
            gridbar(mat);
        }
    }

    /* tail */
    if (blk == 0 && tid == 0) {
        g_diag[mat][NN - 2] = (double)Ah[(size_t)(NN - 2) * NN + (NN - 2)]
                            + (double)Al[(size_t)(NN - 2) * NN + (NN - 2)];
        g_diag[mat][NN - 1] = (double)Ah[(size_t)(NN - 1) * NN + (NN - 1)]
                            + (double)Al[(size_t)(NN - 1) * NN + (NN - 1)];
        g_offd[mat][NN - 2] = (double)Ah[(size_t)(NN - 2) * NN + (NN - 1)]
                            + (double)Al[(size_t)(NN - 2) * NN + (NN - 1)];
        g_offd[mat][NN - 1] = 0.0;
    }
}

/* ------------------------------------------------------------------ */
__global__ __launch_bounds__(256) void k_bisect()
{
    int mat = blockIdx.y;
    __shared__ float sa[NN];
    __shared__ float sb2[NN];
    __shared__ float red[256];
    __shared__ float s_gl, s_gu, s_pm;
    int t = threadIdx.x;
    for (int i = t; i < NN; i += 256) {
        sa[i] = (float)g_diag[mat][i];
        float b = (i < NN - 1) ? (float)g_offd[mat][i] : 0.f;
        sb2[i] = b * b;
    }
    __syncthreads();

    float lo = 3.4e38f, hi = -3.4e38f, mb2 = 0.f;
    for (int i = t; i < NN; i += 256) {
        float bl = (i > 0)      ? sqrtf(sb2[i - 1]) : 0.f;
        float br = (i < NN - 1) ? sqrtf(sb2[i])     : 0.f;
        lo  = fminf(lo, sa[i] - bl - br);
        hi  = fmaxf(hi, sa[i] + bl + br);
        mb2 = fmaxf(mb2, sb2[i]);
    }
    red[t] = lo;  __syncthreads();
    for (int off = 128; off; off >>= 1) { if (t < off) red[t] = fminf(red[t], red[t + off]); __syncthreads(); }
    if (t == 0) s_gl = red[0];
    __syncthreads();
    red[t] = hi;  __syncthreads();
    for (int off = 128; off; off >>= 1) { if (t < off) red[t] = fmaxf(red[t], red[t + off]); __syncthreads(); }
    if (t == 0) s_gu = red[0];
    __syncthreads();
    red[t] = mb2; __syncthreads();
    for (int off = 128; off; off >>= 1) { if (t < off) red[t] = fmaxf(red[t], red[t + off]); __syncthreads(); }
    if (t == 0) s_pm = red[0];
    __syncthreads();

    float span   = s_gu - s_gl;
    float gl     = s_gl - 0.01f * span - 1e-3f;
    float gu     = s_gu + 0.01f * span + 1e-3f;
    float pivmin = fmaxf(s_pm * 1.2e-38f, 1.2e-38f);

    int tgt = blockIdx.x * 256 + t;
    float blo = gl, bhi = gu;
    for (int it = 0; it < 32; it++) {
        float mid = 0.5f * (blo + bhi);
        if (mid <= blo || mid >= bhi) break;
        float d   = sa[0] - mid;
        int   cnt = (d < 0.f);
        #pragma unroll 8
        for (int i = 1; i < NN; i++) {
            d = (sa[i] - mid) - __fdividef(sb2[i - 1], d);
            if (fabsf(d) < pivmin) d = -pivmin;
            cnt += (d < 0.f);
        }
        if (cnt > tgt) bhi = mid; else blo = mid;
    }
    g_eig[mat][tgt] = 0.5f * (blo + bhi);
}

/* ------------------------------------------------------------------ */
__global__ __launch_bounds__(256) void k_final(float* __restrict__ out)
{
    __shared__ double sn[256], sd_[256];
    double gap[2];
    int t = threadIdx.x;
    for (int mat = 0; mat < 2; mat++) {
        double accn = 0.0, accd = 0.0;
        for (int i = t; i < NN; i += 256) {
            double lam = (double)fmaxf(g_eig[mat][i], 0.f);
            double z   = (lam - 1e-4) / 0.01;
            double s   = 1.0 / (1.0 + exp(-z));
            accn += lam * s;
            accd += s;
        }
        sn[t] = accn; sd_[t] = accd;
        __syncthreads();
        for (int off = 128; off; off >>= 1) {
            if (t < off) { sn[t] += sn[t + off]; sd_[t] += sd_[t + off]; }
            __syncthreads();
        }
        gap[mat] = sn[0] / (sd_[0] + 1e-12);
        __syncthreads();
    }
    if (t == 0) {
        double trip = gap[0] - gap[1] + 0.5;
        if (trip < 0.0) trip = 0.0;
        out[0] = (float)(trip + 0.1 * gap[0]);
    }
}

/* ------------------------------------------------------------------ */
extern "C" void kernel_launch(void* const* d_in, const int* in_sizes, int n_in,
                              void* d_out, int out_size)
{
    const float* q   = (const float*)d_in[0];
    const float* pos = (const float*)d_in[1];
    const float* neg = (const float*)d_in[2];
    const float* W   = (const float*)d_in[3];
    (void)in_sizes; (void)n_in; (void)out_size;

    int smem = 2 * PW * CW * (int)sizeof(float);   /* 64 KB */
    cudaFuncSetAttribute((const void*)k_tridiag,
                         cudaFuncAttributeMaxDynamicSharedMemorySize, smem);

    k_proj<<<1024, 256>>>(q, pos, neg, W);
    k_knn<<<1024, 256>>>();
    {
        dim3 ga(512, 2);
        k_assemble<<<ga, 256>>>();
    }
    k_tridiag<<<2 * NB, TPB, smem>>>();
    {
        dim3 gb(16, 2);
        k_bisect<<<gb, 256>>>();
    }
    k_final<<<1, 256>>>((float*)d_out);
}